// round 9
// baseline (speedup 1.0000x reference)
#include <cuda_runtime.h>
#include <cuda_bf16.h>
#include <cstdint>

#define BATCH 8
#define NPTS  8192
#define NCTR  2048          // NPTS * 0.25
#define NSAMP 32
#define C0IN  67
#define C2    128
#define R2    0.25f         // radius^2

// ---------------- scratch (device globals; no allocation allowed) ----------------
__device__ float    g_F0[(size_t)BATCH * NPTS * 64];     // 16 MB, layout (b, j, o)
__device__ unsigned g_progress[BATCH];                   // centers published per batch
__device__ unsigned g_f0done[BATCH];                     // f0 chunks done per batch (8 = ready)

// ---------------- f32x2 packed helpers ----------------
__device__ __forceinline__ unsigned long long pk2(float lo, float hi) {
    unsigned long long r;
    asm("mov.b64 %0, {%1, %2};" : "=l"(r) : "f"(lo), "f"(hi));
    return r;
}
__device__ __forceinline__ unsigned long long pkb(float v) { return pk2(v, v); }
__device__ __forceinline__ void upk2(unsigned long long v, float& lo, float& hi) {
    asm("mov.b64 {%0, %1}, %2;" : "=f"(lo), "=f"(hi) : "l"(v));
}
#define F2FMA(d, a, b, c) asm("fma.rn.f32x2 %0, %1, %2, %3;" : "=l"(d) : "l"(a), "l"(b), "l"(c))
#define F2ADD(d, a, b)    asm("add.rn.f32x2 %0, %1, %2;"     : "=l"(d) : "l"(a), "l"(b))
#define F2MUL(d, a, b)    asm("mul.rn.f32x2 %0, %1, %2;"     : "=l"(d) : "l"(a), "l"(b))

// ---------------- acquire/release helpers ----------------
__device__ __forceinline__ unsigned ld_acq(const unsigned* p) {
    unsigned v;
    asm volatile("ld.acquire.gpu.global.u32 %0, [%1];" : "=r"(v) : "l"(p) : "memory");
    return v;
}
__device__ __forceinline__ void st_rel(unsigned* p, unsigned v) {
    asm volatile("st.release.gpu.global.u32 [%0], %1;" :: "l"(p), "r"(v) : "memory");
}

// =====================================================================
// reset: clear the inter-block flags (needed per graph replay)
// =====================================================================
__global__ void reset_kernel()
{
    if (threadIdx.x < BATCH) {
        g_progress[threadIdx.x] = 0;
        g_f0done[threadIdx.x]  = 0;
    }
}

// =====================================================================
// mega-kernel: bid 0-7 FPS | bid 8-71 F0 | bid 72+ ballq+MLP workers
// =====================================================================
#define MLPT 512
#define XROW 260
#define SMEM_FLOATS (4096 + 8192 + 64*XROW + 64*XROW + 256 + 64 + 128)
#define GRID_TOTAL (8 + 64 + BATCH * NCTR / 8)

__global__ void __launch_bounds__(MLPT, 1)
mega_kernel(const float* __restrict__ pos,
            const float* __restrict__ features,
            const float* __restrict__ w0, const float* __restrict__ b0,
            const float* __restrict__ w1, const float* __restrict__ b1,
            const float* __restrict__ w2, const float* __restrict__ b2,
            float* __restrict__ new_xyz,
            float* __restrict__ out_feat)
{
    const int bid = blockIdx.x;
    const int tid = threadIdx.x;
    extern __shared__ float sm[];

    // =================================================================
    // ROLE 1: FPS — 512 threads, f32x2 update, single 64-bit RED.MAX
    //         cross-warp reduction (key = dist_bits<<32 | 8192-idx).
    // =================================================================
    if (bid < 8) {
        const int b = bid;
        const int t = tid;
        const float* pb = pos + (size_t)b * NPTS * 3;

        unsigned long long xp[8], yp[8], zp[8];
        float dm[16];
#pragma unroll
        for (int k = 0; k < 8; k++) {
            int p0 = t + (2 * k) * 512;
            int p1 = p0 + 512;
            xp[k] = pk2(pb[3 * p0 + 0], pb[3 * p1 + 0]);
            yp[k] = pk2(pb[3 * p0 + 1], pb[3 * p1 + 1]);
            zp[k] = pk2(pb[3 * p0 + 2], pb[3 * p1 + 2]);
            dm[2 * k] = 1e10f; dm[2 * k + 1] = 1e10f;
        }

        __shared__ unsigned long long s_key[3];     // triple-buffered winner key
        if (t < 3) s_key[t] = 0ULL;

        float cx = pb[0], cy = pb[1], cz = pb[2];
        if (t == 0) {
            float* nz = new_xyz + (size_t)b * NCTR * 3;
            nz[0] = cx; nz[1] = cy; nz[2] = cz;
        }
        __syncthreads();

        int buf = 1, rst = 0;    // s=1: slot 1; reset slot (s+2)%3 = 0

        for (int s = 1; s < NCTR; ++s) {
            // ---- distance update (f32x2), min into dm only ----
            const unsigned long long nx  = pkb(-cx);
            const unsigned long long ny  = pkb(-cy);
            const unsigned long long nzp = pkb(-cz);
#pragma unroll
            for (int k = 0; k < 8; k++) {
                unsigned long long dx, dy, dz, sq;
                F2ADD(dx, xp[k], nx);
                F2ADD(dy, yp[k], ny);
                F2ADD(dz, zp[k], nzp);
                F2MUL(sq, dx, dx);
                F2FMA(sq, dy, dy, sq);
                F2FMA(sq, dz, dz, sq);      // == scalar fmaf(dz,dz,fmaf(dy,dy,dx*dx))
                float lo, hi; upk2(sq, lo, hi);
                dm[2 * k]     = fminf(dm[2 * k], lo);
                dm[2 * k + 1] = fminf(dm[2 * k + 1], hi);
            }

            // ---- pairwise max tree over 16 dm values (depth 4) ----
            float t8[8];
#pragma unroll
            for (int i = 0; i < 8; i++) t8[i] = fmaxf(dm[2 * i], dm[2 * i + 1]);
            float t4a = fmaxf(t8[0], t8[1]), t4b = fmaxf(t8[2], t8[3]);
            float t4c = fmaxf(t8[4], t8[5]), t4d = fmaxf(t8[6], t8[7]);
            float m = fmaxf(fmaxf(t4a, t4b), fmaxf(t4c, t4d));

            // ---- warp max; tying threads RED.MAX the fused key ----
            unsigned mb = __float_as_uint(m);            // d >= 0: order-preserving
            unsigned wmax = __reduce_max_sync(0xffffffffu, mb);
            if (mb == wmax) {
                unsigned best = 0;
#pragma unroll
                for (int j = 15; j >= 0; j--)
                    if (__float_as_uint(dm[j]) == wmax) best = (unsigned)((j << 9) + t);
                atomicMax(&s_key[buf],
                          ((unsigned long long)wmax << 32) | (8192u - best));
            }
            __syncthreads();                             // the ONLY barrier per step

            unsigned long long kk = s_key[buf];
            unsigned gidx = 8192u - (unsigned)kk;

            const float* pp = pb + 3 * (size_t)gidx;     // broadcast LDG, L1-hit
            cx = pp[0]; cy = pp[1]; cz = pp[2];
            if (t == 0) {
                float* nz = new_xyz + ((size_t)b * NCTR + s) * 3;
                nz[0] = cx; nz[1] = cy; nz[2] = cz;
                s_key[rst] = 0ULL;                       // safe: 2 barriers before reuse
                if ((s & 7) == 7) st_rel(&g_progress[b], (unsigned)(s + 1));
            }
            buf = (buf == 2) ? 0 : buf + 1;
            rst = (rst == 2) ? 0 : rst + 1;
        }
        return;
    }

    // =================================================================
    // ROLE 2: F0 precompute. 64 blocks: batch = fb>>3, 1024-pt chunk.
    // =================================================================
    if (bid < 72) {
        const int fb = bid - 8;
        const int b = fb >> 3;
        const int j0 = (fb & 7) * 1024;
        float (*w0t)[64] = (float(*)[64])sm;     // [c][o]

        for (int i = tid; i < 64 * 64; i += MLPT) {
            int c = i >> 6, o = i & 63;
            w0t[c][o] = w0[o * C0IN + 3 + c];
        }
        __syncthreads();

#pragma unroll
        for (int rep = 0; rep < 2; rep++) {
            const int j = j0 + rep * 512 + tid;
            float acc[64];
#pragma unroll
            for (int o = 0; o < 64; o++) acc[o] = 0.0f;

            for (int c = 0; c < 64; c++) {
                float fc = features[((size_t)b * 64 + c) * NPTS + j];
#pragma unroll
                for (int o4 = 0; o4 < 64; o4 += 4) {
                    float4 wv = *(const float4*)&w0t[c][o4];
                    acc[o4 + 0] = fmaf(wv.x, fc, acc[o4 + 0]);
                    acc[o4 + 1] = fmaf(wv.y, fc, acc[o4 + 1]);
                    acc[o4 + 2] = fmaf(wv.z, fc, acc[o4 + 2]);
                    acc[o4 + 3] = fmaf(wv.w, fc, acc[o4 + 3]);
                }
            }
            float* op = g_F0 + ((size_t)b * NPTS + j) * 64;
#pragma unroll
            for (int o4 = 0; o4 < 64; o4 += 4)
                *(float4*)(op + o4) = make_float4(acc[o4], acc[o4+1], acc[o4+2], acc[o4+3]);
        }

        __threadfence();
        __syncthreads();
        if (tid == 0) atomicAdd(&g_f0done[b], 1u);
        return;
    }

    // =================================================================
    // ROLE 3: worker — wait for data, in-block ballq, fused MLP+maxpool
    // =================================================================
    {
        const int g = bid - 72;
        const int b = g >> 8;
        const int s0 = (g & 255) * 8;

        float* sW1 = sm;                       // [c][o] 64x64
        float* sW2 = sm + 4096;                // [c][o] 64x128
        float* sX0 = sm + 12288;               // [c][m] 64 x XROW
        float* sX1 = sm + 12288 + 64 * XROW;
        float4* sWXB = (float4*)(sm + 12288 + 128 * XROW);
        float* sB1 = sm + 12288 + 128 * XROW + 256;
        float* sB2 = sB1 + 64;
        __shared__ int s_bq[8][NSAMP];

        // ---- load weights while waiting is pending ----
        for (int i = tid; i < 4096; i += MLPT) {
            int c = i >> 6, o = i & 63;
            sW1[c * 64 + o] = w1[o * 64 + c];
        }
        for (int i = tid; i < 8192; i += MLPT) {
            int c = i >> 7, o = i & 127;
            sW2[c * 128 + o] = w2[o * 64 + c];
        }
        if (tid < 64) {
            sWXB[tid] = make_float4(w0[tid * C0IN + 0], w0[tid * C0IN + 1],
                                    w0[tid * C0IN + 2], b0[tid]);
            sB1[tid] = b1[tid];
        }
        if (tid < 128) sB2[tid] = b2[tid];

        // ---- wait for FPS centers + F0 of this batch ----
        if (tid == 0) {
            while (ld_acq(&g_progress[b]) < (unsigned)(s0 + 8)) __nanosleep(256);
            while (ld_acq(&g_f0done[b]) < 8u) __nanosleep(256);
        }
        __syncthreads();

        // ---- in-block ball query: warp w handles center s0+w ----
        {
            const int lane = tid & 31, w = tid >> 5;
            if (w < 8) {
                const int sg = s0 + w;
                const float* cz = new_xyz + ((size_t)b * NCTR + sg) * 3;
                const float cx = cz[0], cy = cz[1], czz = cz[2];
                const float* pb = pos + (size_t)b * NPTS * 3;

                int cnt = 0, first = -1;
                for (int j0 = 0; j0 < NPTS; j0 += 32) {
                    int j = j0 + lane;
                    float dx = pb[3 * j + 0] - cx;
                    float dy = pb[3 * j + 1] - cy;
                    float dz = pb[3 * j + 2] - czz;
                    float d = fmaf(dz, dz, fmaf(dy, dy, dx * dx));
                    bool hit = d < R2;
                    unsigned bal = __ballot_sync(0xffffffffu, hit);
                    if (bal) {
                        if (first < 0) first = j0 + __ffs((int)bal) - 1;
                        int pre = __popc(bal & ((1u << lane) - 1u));
                        if (hit && cnt + pre < NSAMP) s_bq[w][cnt + pre] = j;
                        cnt += __popc(bal);
                        if (cnt >= NSAMP) break;
                    }
                }
                if (cnt < NSAMP) {
                    int pad = (first < 0) ? 0 : first;
                    if (lane >= cnt) s_bq[w][lane] = pad;
                }
            }
        }
        __syncthreads();

        // ---- phase A: build X0 (layer0 output), 256 rows x 64 ch ----
        {
            const int r = tid >> 1;
            const int h = tid & 1;
            const int o0 = h * 32;
            const int ci = r >> 5, k = r & 31;
            const int sg = s0 + ci;
            const int j = s_bq[ci][k];

            const float* pp = pos + ((size_t)b * NPTS + j) * 3;
            const float* cz = new_xyz + ((size_t)b * NCTR + sg) * 3;
            float rx = pp[0] - cz[0];
            float ry = pp[1] - cz[1];
            float rz = pp[2] - cz[2];
            const float* fp = g_F0 + ((size_t)b * NPTS + j) * 64 + o0;

#pragma unroll
            for (int o4 = 0; o4 < 32; o4 += 4) {
                float4 f = *(const float4*)(fp + o4);
                float fv[4] = { f.x, f.y, f.z, f.w };
#pragma unroll
                for (int i = 0; i < 4; i++) {
                    float4 wb = sWXB[o0 + o4 + i];
                    float v = fv[i] + wb.x * rx + wb.y * ry + wb.z * rz + wb.w;
                    sX0[(o0 + o4 + i) * XROW + r] = fmaxf(v, 0.0f);
                }
            }
        }
        __syncthreads();

        const int tm = tid & 63, tn = tid >> 6;
        const int m0 = tm * 4;

        // ---- GEMM1: X1 = relu(X0 @ W1^T + b1), 256x64, f32x2 ----
        {
            const int n0 = tn * 8;
            unsigned long long acc2[16];
#pragma unroll
            for (int i = 0; i < 16; i++) acc2[i] = 0ULL;

#pragma unroll 8
            for (int c = 0; c < 64; c++) {
                float4 a  = *(const float4*)&sX0[c * XROW + m0];
                float4 bA = *(const float4*)&sW1[c * 64 + n0];
                float4 bB = *(const float4*)&sW1[c * 64 + n0 + 4];
                unsigned long long bp[4] = { pk2(bA.x, bA.y), pk2(bA.z, bA.w),
                                             pk2(bB.x, bB.y), pk2(bB.z, bB.w) };
                unsigned long long ap[4] = { pkb(a.x), pkb(a.y), pkb(a.z), pkb(a.w) };
#pragma unroll
                for (int i = 0; i < 4; i++)
#pragma unroll
                    for (int jp = 0; jp < 4; jp++)
                        F2FMA(acc2[i * 4 + jp], ap[i], bp[jp], acc2[i * 4 + jp]);
            }

#pragma unroll
            for (int jp = 0; jp < 4; jp++) {
                float lo[4], hi[4];
#pragma unroll
                for (int i = 0; i < 4; i++) upk2(acc2[i * 4 + jp], lo[i], hi[i]);
                float bb0 = sB1[n0 + 2 * jp], bb1 = sB1[n0 + 2 * jp + 1];
                float4 v0, v1;
                v0.x = fmaxf(lo[0] + bb0, 0.0f); v0.y = fmaxf(lo[1] + bb0, 0.0f);
                v0.z = fmaxf(lo[2] + bb0, 0.0f); v0.w = fmaxf(lo[3] + bb0, 0.0f);
                v1.x = fmaxf(hi[0] + bb1, 0.0f); v1.y = fmaxf(hi[1] + bb1, 0.0f);
                v1.z = fmaxf(hi[2] + bb1, 0.0f); v1.w = fmaxf(hi[3] + bb1, 0.0f);
                *(float4*)&sX1[(n0 + 2 * jp)     * XROW + m0] = v0;
                *(float4*)&sX1[(n0 + 2 * jp + 1) * XROW + m0] = v1;
            }
        }
        __syncthreads();

        // ---- GEMM2: 256x128, f32x2, fold max+bias+relu ----
        {
            const int n2 = tn * 16;
            unsigned long long acc2[32];
#pragma unroll
            for (int i = 0; i < 32; i++) acc2[i] = 0ULL;

#pragma unroll 4
            for (int c = 0; c < 64; c++) {
                float4 a = *(const float4*)&sX1[c * XROW + m0];
                unsigned long long ap[4] = { pkb(a.x), pkb(a.y), pkb(a.z), pkb(a.w) };
                unsigned long long bp[8];
#pragma unroll
                for (int q = 0; q < 4; q++) {
                    float4 bb = *(const float4*)&sW2[c * 128 + n2 + 4 * q];
                    bp[2 * q]     = pk2(bb.x, bb.y);
                    bp[2 * q + 1] = pk2(bb.z, bb.w);
                }
#pragma unroll
                for (int i = 0; i < 4; i++)
#pragma unroll
                    for (int jp = 0; jp < 8; jp++)
                        F2FMA(acc2[i * 8 + jp], ap[i], bp[jp], acc2[i * 8 + jp]);
            }

            const int center = tm >> 3;
#pragma unroll
            for (int jp = 0; jp < 8; jp++) {
                float lo[4], hi[4];
#pragma unroll
                for (int i = 0; i < 4; i++) upk2(acc2[i * 8 + jp], lo[i], hi[i]);
                float vlo = fmaxf(fmaxf(lo[0], lo[1]), fmaxf(lo[2], lo[3]));
                float vhi = fmaxf(fmaxf(hi[0], hi[1]), fmaxf(hi[2], hi[3]));
                vlo = fmaxf(vlo, __shfl_xor_sync(0xffffffffu, vlo, 1));
                vhi = fmaxf(vhi, __shfl_xor_sync(0xffffffffu, vhi, 1));
                vlo = fmaxf(vlo, __shfl_xor_sync(0xffffffffu, vlo, 2));
                vhi = fmaxf(vhi, __shfl_xor_sync(0xffffffffu, vhi, 2));
                vlo = fmaxf(vlo, __shfl_xor_sync(0xffffffffu, vlo, 4));
                vhi = fmaxf(vhi, __shfl_xor_sync(0xffffffffu, vhi, 4));
                if ((tm & 7) == 0) {
                    int n = n2 + 2 * jp;
                    out_feat[((size_t)b * C2 + n)     * NCTR + (s0 + center)] =
                        fmaxf(vlo + sB2[n], 0.0f);
                    out_feat[((size_t)b * C2 + n + 1) * NCTR + (s0 + center)] =
                        fmaxf(vhi + sB2[n + 1], 0.0f);
                }
            }
        }
    }
}

// =====================================================================
extern "C" void kernel_launch(void* const* d_in, const int* in_sizes, int n_in,
                              void* d_out, int out_size)
{
    const float* pos      = (const float*)d_in[0];
    const float* features = (const float*)d_in[1];
    const float* w0       = (const float*)d_in[2];
    const float* b0       = (const float*)d_in[3];
    const float* w1       = (const float*)d_in[4];
    const float* b1       = (const float*)d_in[5];
    const float* w2       = (const float*)d_in[6];
    const float* b2       = (const float*)d_in[7];

    float* out = (float*)d_out;
    float* new_xyz  = out;                               // (8, 2048, 3)
    float* out_feat = out + (size_t)BATCH * NCTR * 3;    // (8, 128, 2048)

    reset_kernel<<<1, 32>>>();

    cudaFuncSetAttribute(mega_kernel,
                         cudaFuncAttributeMaxDynamicSharedMemorySize,
                         SMEM_FLOATS * sizeof(float));
    mega_kernel<<<GRID_TOTAL, MLPT, SMEM_FLOATS * sizeof(float)>>>(
        pos, features, w0, b0, w1, b1, w2, b2, new_xyz, out_feat);
}

// round 10
// speedup vs baseline: 1.5021x; 1.5021x over previous
#include <cuda_runtime.h>
#include <cuda_bf16.h>
#include <cstdint>

#define BATCH 8
#define NPTS  8192
#define NCTR  2048          // NPTS * 0.25
#define NSAMP 32
#define C0IN  67
#define C2    128
#define R2    0.25f         // radius^2

// ---------------- scratch (device globals; no allocation allowed) ----------------
__device__ float    g_F0[(size_t)BATCH * NPTS * 64];     // 16 MB, layout (b, j, o)
__device__ unsigned g_progress[BATCH];                   // centers published per batch
__device__ unsigned g_f0done[BATCH];                     // f0 chunks done per batch (8 = ready)

// ---------------- f32x2 packed helpers ----------------
__device__ __forceinline__ unsigned long long pk2(float lo, float hi) {
    unsigned long long r;
    asm("mov.b64 %0, {%1, %2};" : "=l"(r) : "f"(lo), "f"(hi));
    return r;
}
__device__ __forceinline__ unsigned long long pkb(float v) { return pk2(v, v); }
__device__ __forceinline__ void upk2(unsigned long long v, float& lo, float& hi) {
    asm("mov.b64 {%0, %1}, %2;" : "=f"(lo), "=f"(hi) : "l"(v));
}
#define F2FMA(d, a, b, c) asm("fma.rn.f32x2 %0, %1, %2, %3;" : "=l"(d) : "l"(a), "l"(b), "l"(c))
#define F2ADD(d, a, b)    asm("add.rn.f32x2 %0, %1, %2;"     : "=l"(d) : "l"(a), "l"(b))
#define F2MUL(d, a, b)    asm("mul.rn.f32x2 %0, %1, %2;"     : "=l"(d) : "l"(a), "l"(b))

// ---------------- acquire/release helpers ----------------
__device__ __forceinline__ unsigned ld_acq(const unsigned* p) {
    unsigned v;
    asm volatile("ld.acquire.gpu.global.u32 %0, [%1];" : "=r"(v) : "l"(p) : "memory");
    return v;
}
__device__ __forceinline__ void st_rel(unsigned* p, unsigned v) {
    asm volatile("st.release.gpu.global.u32 [%0], %1;" :: "l"(p), "r"(v) : "memory");
}

// =====================================================================
// reset: clear the inter-block flags (needed per graph replay)
// =====================================================================
__global__ void reset_kernel()
{
    if (threadIdx.x < BATCH) {
        g_progress[threadIdx.x] = 0;
        g_f0done[threadIdx.x]  = 0;
    }
}

// =====================================================================
// mega-kernel: bid 0-7 FPS | bid 8-71 F0 | bid 72+ ballq+MLP workers
// Worker groups are INTERLEAVED across batches so the resident worker
// set matches the FPS production wavefront (kills the drain tail).
// =====================================================================
#define MLPT 512
#define XROW 260
#define SMEM_FLOATS (4096 + 8192 + 64*XROW + 64*XROW + 256 + 64 + 128)
#define GRID_TOTAL (8 + 64 + BATCH * NCTR / 8)

__global__ void __launch_bounds__(MLPT, 1)
mega_kernel(const float* __restrict__ pos,
            const float* __restrict__ features,
            const float* __restrict__ w0, const float* __restrict__ b0,
            const float* __restrict__ w1, const float* __restrict__ b1,
            const float* __restrict__ w2, const float* __restrict__ b2,
            float* __restrict__ new_xyz,
            float* __restrict__ out_feat)
{
    const int bid = blockIdx.x;
    const int tid = threadIdx.x;
    extern __shared__ float sm[];

    // =================================================================
    // ROLE 1: FPS (round-8 structure: REDUX tail, no smem atomics)
    // =================================================================
    if (bid < 8) {
        const int b = bid;
        const int t = tid;
        const int lane = t & 31, w = t >> 5;
        const float* pb = pos + (size_t)b * NPTS * 3;

        unsigned long long xp[8], yp[8], zp[8];
        float dm[16];
#pragma unroll
        for (int k = 0; k < 8; k++) {
            int p0 = t + (2 * k) * 512;
            int p1 = p0 + 512;
            xp[k] = pk2(pb[3 * p0 + 0], pb[3 * p1 + 0]);
            yp[k] = pk2(pb[3 * p0 + 1], pb[3 * p1 + 1]);
            zp[k] = pk2(pb[3 * p0 + 2], pb[3 * p1 + 2]);
            dm[2 * k] = 1e10f; dm[2 * k + 1] = 1e10f;
        }

        __shared__ unsigned s_vhi[2][16];
        __shared__ unsigned s_vlo[2][16];

        float cx = pb[0], cy = pb[1], cz = pb[2];
        if (t == 0) {
            float* nz = new_xyz + (size_t)b * NCTR * 3;
            nz[0] = cx; nz[1] = cy; nz[2] = cz;
        }

        for (int s = 1; s < NCTR; ++s) {
            const int buf = s & 1;

            const unsigned long long nx  = pkb(-cx);
            const unsigned long long ny  = pkb(-cy);
            const unsigned long long nzp = pkb(-cz);
            float m = 0.0f;
#pragma unroll
            for (int k = 0; k < 8; k++) {
                unsigned long long dx, dy, dz, sq;
                F2ADD(dx, xp[k], nx);
                F2ADD(dy, yp[k], ny);
                F2ADD(dz, zp[k], nzp);
                F2MUL(sq, dx, dx);
                F2FMA(sq, dy, dy, sq);
                F2FMA(sq, dz, dz, sq);      // == scalar fmaf chain (exact)
                float lo, hi; upk2(sq, lo, hi);
                dm[2 * k]     = fminf(dm[2 * k], lo);
                dm[2 * k + 1] = fminf(dm[2 * k + 1], hi);
                m = fmaxf(m, dm[2 * k]);
                m = fmaxf(m, dm[2 * k + 1]);
            }

            unsigned mb = __float_as_uint(m);
            unsigned wmax = __reduce_max_sync(0xffffffffu, mb);
            unsigned cand = 0xffffffffu;
            if (mb == wmax) {
#pragma unroll
                for (int j = 15; j >= 0; j--)
                    if (__float_as_uint(dm[j]) == wmax) cand = (unsigned)((j << 9) + t);
            }
            unsigned widx = __reduce_min_sync(0xffffffffu, cand);
            if (lane == 0) {
                s_vhi[buf][w] = wmax;
                s_vlo[buf][w] = 8192u - widx;
            }
            __syncthreads();

            unsigned v   = (lane < 16) ? s_vhi[buf][lane] : 0u;
            unsigned ghi = __reduce_max_sync(0xffffffffu, v);
            unsigned lo2 = (lane < 16 && v == ghi) ? s_vlo[buf][lane] : 0u;
            unsigned glo = __reduce_max_sync(0xffffffffu, lo2);
            unsigned gidx = 8192u - glo;

            const float* pp = pb + 3 * (size_t)gidx;
            cx = pp[0]; cy = pp[1]; cz = pp[2];
            if (t == 0) {
                float* nz = new_xyz + ((size_t)b * NCTR + s) * 3;
                nz[0] = cx; nz[1] = cy; nz[2] = cz;
                if ((s & 7) == 7) st_rel(&g_progress[b], (unsigned)(s + 1));
            }
        }
        return;
    }

    // =================================================================
    // ROLE 2: F0 precompute. 64 blocks: batch = fb>>3, 1024-pt chunk.
    // =================================================================
    if (bid < 72) {
        const int fb = bid - 8;
        const int b = fb >> 3;
        const int j0 = (fb & 7) * 1024;
        float (*w0t)[64] = (float(*)[64])sm;     // [c][o]

        for (int i = tid; i < 64 * 64; i += MLPT) {
            int c = i >> 6, o = i & 63;
            w0t[c][o] = w0[o * C0IN + 3 + c];
        }
        __syncthreads();

#pragma unroll
        for (int rep = 0; rep < 2; rep++) {
            const int j = j0 + rep * 512 + tid;
            float acc[64];
#pragma unroll
            for (int o = 0; o < 64; o++) acc[o] = 0.0f;

            for (int c = 0; c < 64; c++) {
                float fc = features[((size_t)b * 64 + c) * NPTS + j];
#pragma unroll
                for (int o4 = 0; o4 < 64; o4 += 4) {
                    float4 wv = *(const float4*)&w0t[c][o4];
                    acc[o4 + 0] = fmaf(wv.x, fc, acc[o4 + 0]);
                    acc[o4 + 1] = fmaf(wv.y, fc, acc[o4 + 1]);
                    acc[o4 + 2] = fmaf(wv.z, fc, acc[o4 + 2]);
                    acc[o4 + 3] = fmaf(wv.w, fc, acc[o4 + 3]);
                }
            }
            float* op = g_F0 + ((size_t)b * NPTS + j) * 64;
#pragma unroll
            for (int o4 = 0; o4 < 64; o4 += 4)
                *(float4*)(op + o4) = make_float4(acc[o4], acc[o4+1], acc[o4+2], acc[o4+3]);
        }

        __threadfence();
        __syncthreads();
        if (tid == 0) atomicAdd(&g_f0done[b], 1u);
        return;
    }

    // =================================================================
    // ROLE 3: worker — INTERLEAVED mapping: batch = g&7, group = g>>3
    // =================================================================
    {
        const int g = bid - 72;
        const int b = g & 7;
        const int s0 = (g >> 3) * 8;

        float* sW1 = sm;                       // [c][o] 64x64
        float* sW2 = sm + 4096;                // [c][o] 64x128
        float* sX0 = sm + 12288;               // [c][m] 64 x XROW
        float* sX1 = sm + 12288 + 64 * XROW;
        float4* sWXB = (float4*)(sm + 12288 + 128 * XROW);
        float* sB1 = sm + 12288 + 128 * XROW + 256;
        float* sB2 = sB1 + 64;
        __shared__ int s_bq[8][NSAMP];

        // ---- load weights while waiting is pending ----
        for (int i = tid; i < 4096; i += MLPT) {
            int c = i >> 6, o = i & 63;
            sW1[c * 64 + o] = w1[o * 64 + c];
        }
        for (int i = tid; i < 8192; i += MLPT) {
            int c = i >> 7, o = i & 127;
            sW2[c * 128 + o] = w2[o * 64 + c];
        }
        if (tid < 64) {
            sWXB[tid] = make_float4(w0[tid * C0IN + 0], w0[tid * C0IN + 1],
                                    w0[tid * C0IN + 2], b0[tid]);
            sB1[tid] = b1[tid];
        }
        if (tid < 128) sB2[tid] = b2[tid];

        // ---- wait for FPS centers + F0 of this batch ----
        if (tid == 0) {
            while (ld_acq(&g_progress[b]) < (unsigned)(s0 + 8)) __nanosleep(1024);
            while (ld_acq(&g_f0done[b]) < 8u) __nanosleep(1024);
        }
        __syncthreads();

        // ---- in-block ball query: warp w handles center s0+w ----
        {
            const int lane = tid & 31, w = tid >> 5;
            if (w < 8) {
                const int sg = s0 + w;
                const float* cz = new_xyz + ((size_t)b * NCTR + sg) * 3;
                const float cx = cz[0], cy = cz[1], czz = cz[2];
                const float* pb = pos + (size_t)b * NPTS * 3;

                int cnt = 0, first = -1;
                for (int j0 = 0; j0 < NPTS; j0 += 32) {
                    int j = j0 + lane;
                    float dx = pb[3 * j + 0] - cx;
                    float dy = pb[3 * j + 1] - cy;
                    float dz = pb[3 * j + 2] - czz;
                    float d = fmaf(dz, dz, fmaf(dy, dy, dx * dx));
                    bool hit = d < R2;
                    unsigned bal = __ballot_sync(0xffffffffu, hit);
                    if (bal) {
                        if (first < 0) first = j0 + __ffs((int)bal) - 1;
                        int pre = __popc(bal & ((1u << lane) - 1u));
                        if (hit && cnt + pre < NSAMP) s_bq[w][cnt + pre] = j;
                        cnt += __popc(bal);
                        if (cnt >= NSAMP) break;
                    }
                }
                if (cnt < NSAMP) {
                    int pad = (first < 0) ? 0 : first;
                    if (lane >= cnt) s_bq[w][lane] = pad;
                }
            }
        }
        __syncthreads();

        // ---- phase A: build X0 (layer0 output), 256 rows x 64 ch ----
        {
            const int r = tid >> 1;
            const int h = tid & 1;
            const int o0 = h * 32;
            const int ci = r >> 5, k = r & 31;
            const int sg = s0 + ci;
            const int j = s_bq[ci][k];

            const float* pp = pos + ((size_t)b * NPTS + j) * 3;
            const float* cz = new_xyz + ((size_t)b * NCTR + sg) * 3;
            float rx = pp[0] - cz[0];
            float ry = pp[1] - cz[1];
            float rz = pp[2] - cz[2];
            const float* fp = g_F0 + ((size_t)b * NPTS + j) * 64 + o0;

#pragma unroll
            for (int o4 = 0; o4 < 32; o4 += 4) {
                float4 f = *(const float4*)(fp + o4);
                float fv[4] = { f.x, f.y, f.z, f.w };
#pragma unroll
                for (int i = 0; i < 4; i++) {
                    float4 wb = sWXB[o0 + o4 + i];
                    float v = fv[i] + wb.x * rx + wb.y * ry + wb.z * rz + wb.w;
                    sX0[(o0 + o4 + i) * XROW + r] = fmaxf(v, 0.0f);
                }
            }
        }
        __syncthreads();

        const int tm = tid & 63, tn = tid >> 6;
        const int m0 = tm * 4;

        // ---- GEMM1: X1 = relu(X0 @ W1^T + b1), 256x64, f32x2 ----
        {
            const int n0 = tn * 8;
            unsigned long long acc2[16];
#pragma unroll
            for (int i = 0; i < 16; i++) acc2[i] = 0ULL;

#pragma unroll 8
            for (int c = 0; c < 64; c++) {
                float4 a  = *(const float4*)&sX0[c * XROW + m0];
                float4 bA = *(const float4*)&sW1[c * 64 + n0];
                float4 bB = *(const float4*)&sW1[c * 64 + n0 + 4];
                unsigned long long bp[4] = { pk2(bA.x, bA.y), pk2(bA.z, bA.w),
                                             pk2(bB.x, bB.y), pk2(bB.z, bB.w) };
                unsigned long long ap[4] = { pkb(a.x), pkb(a.y), pkb(a.z), pkb(a.w) };
#pragma unroll
                for (int i = 0; i < 4; i++)
#pragma unroll
                    for (int jp = 0; jp < 4; jp++)
                        F2FMA(acc2[i * 4 + jp], ap[i], bp[jp], acc2[i * 4 + jp]);
            }

#pragma unroll
            for (int jp = 0; jp < 4; jp++) {
                float lo[4], hi[4];
#pragma unroll
                for (int i = 0; i < 4; i++) upk2(acc2[i * 4 + jp], lo[i], hi[i]);
                float bb0 = sB1[n0 + 2 * jp], bb1 = sB1[n0 + 2 * jp + 1];
                float4 v0, v1;
                v0.x = fmaxf(lo[0] + bb0, 0.0f); v0.y = fmaxf(lo[1] + bb0, 0.0f);
                v0.z = fmaxf(lo[2] + bb0, 0.0f); v0.w = fmaxf(lo[3] + bb0, 0.0f);
                v1.x = fmaxf(hi[0] + bb1, 0.0f); v1.y = fmaxf(hi[1] + bb1, 0.0f);
                v1.z = fmaxf(hi[2] + bb1, 0.0f); v1.w = fmaxf(hi[3] + bb1, 0.0f);
                *(float4*)&sX1[(n0 + 2 * jp)     * XROW + m0] = v0;
                *(float4*)&sX1[(n0 + 2 * jp + 1) * XROW + m0] = v1;
            }
        }
        __syncthreads();

        // ---- GEMM2: 256x128, f32x2, fold max+bias+relu ----
        {
            const int n2 = tn * 16;
            unsigned long long acc2[32];
#pragma unroll
            for (int i = 0; i < 32; i++) acc2[i] = 0ULL;

#pragma unroll 4
            for (int c = 0; c < 64; c++) {
                float4 a = *(const float4*)&sX1[c * XROW + m0];
                unsigned long long ap[4] = { pkb(a.x), pkb(a.y), pkb(a.z), pkb(a.w) };
                unsigned long long bp[8];
#pragma unroll
                for (int q = 0; q < 4; q++) {
                    float4 bb = *(const float4*)&sW2[c * 128 + n2 + 4 * q];
                    bp[2 * q]     = pk2(bb.x, bb.y);
                    bp[2 * q + 1] = pk2(bb.z, bb.w);
                }
#pragma unroll
                for (int i = 0; i < 4; i++)
#pragma unroll
                    for (int jp = 0; jp < 8; jp++)
                        F2FMA(acc2[i * 8 + jp], ap[i], bp[jp], acc2[i * 8 + jp]);
            }

            const int center = tm >> 3;
#pragma unroll
            for (int jp = 0; jp < 8; jp++) {
                float lo[4], hi[4];
#pragma unroll
                for (int i = 0; i < 4; i++) upk2(acc2[i * 8 + jp], lo[i], hi[i]);
                float vlo = fmaxf(fmaxf(lo[0], lo[1]), fmaxf(lo[2], lo[3]));
                float vhi = fmaxf(fmaxf(hi[0], hi[1]), fmaxf(hi[2], hi[3]));
                vlo = fmaxf(vlo, __shfl_xor_sync(0xffffffffu, vlo, 1));
                vhi = fmaxf(vhi, __shfl_xor_sync(0xffffffffu, vhi, 1));
                vlo = fmaxf(vlo, __shfl_xor_sync(0xffffffffu, vlo, 2));
                vhi = fmaxf(vhi, __shfl_xor_sync(0xffffffffu, vhi, 2));
                vlo = fmaxf(vlo, __shfl_xor_sync(0xffffffffu, vlo, 4));
                vhi = fmaxf(vhi, __shfl_xor_sync(0xffffffffu, vhi, 4));
                if ((tm & 7) == 0) {
                    int n = n2 + 2 * jp;
                    out_feat[((size_t)b * C2 + n)     * NCTR + (s0 + center)] =
                        fmaxf(vlo + sB2[n], 0.0f);
                    out_feat[((size_t)b * C2 + n + 1) * NCTR + (s0 + center)] =
                        fmaxf(vhi + sB2[n + 1], 0.0f);
                }
            }
        }
    }
}

// =====================================================================
extern "C" void kernel_launch(void* const* d_in, const int* in_sizes, int n_in,
                              void* d_out, int out_size)
{
    const float* pos      = (const float*)d_in[0];
    const float* features = (const float*)d_in[1];
    const float* w0       = (const float*)d_in[2];
    const float* b0       = (const float*)d_in[3];
    const float* w1       = (const float*)d_in[4];
    const float* b1       = (const float*)d_in[5];
    const float* w2       = (const float*)d_in[6];
    const float* b2       = (const float*)d_in[7];

    float* out = (float*)d_out;
    float* new_xyz  = out;                               // (8, 2048, 3)
    float* out_feat = out + (size_t)BATCH * NCTR * 3;    // (8, 128, 2048)

    reset_kernel<<<1, 32>>>();

    cudaFuncSetAttribute(mega_kernel,
                         cudaFuncAttributeMaxDynamicSharedMemorySize,
                         SMEM_FLOATS * sizeof(float));
    mega_kernel<<<GRID_TOTAL, MLPT, SMEM_FLOATS * sizeof(float)>>>(
        pos, features, w0, b0, w1, b1, w2, b2, new_xyz, out_feat);
}